// round 1
// baseline (speedup 1.0000x reference)
#include <cuda_runtime.h>
#include <math.h>

// Problem constants
#define BB      2
#define TT      2048
#define DMODEL  2048
#define NH      32
#define NKV     8
#define HDIM    64
#define QKVC    3072            // 2048 (Q) + 512 (K) + 512 (V)
#define ROWS    (BB * TT)       // 4096

// Scratch (allocation-free rule: __device__ globals)
__device__ float g_qkv[(size_t)ROWS * QKVC];   // [row][3072]
__device__ float g_att[(size_t)ROWS * DMODEL]; // attention output (B,T,H*hd)
__device__ float g_cos[TT * 32];
__device__ float g_sin[TT * 32];

// ---------------------------------------------------------------------------
// RoPE table: cos/sin of fp32 angle (t * fp32(invfreq)), trig in double so
// --use_fast_math cannot degrade accuracy. 65536 elements, negligible cost.
// ---------------------------------------------------------------------------
__global__ void rope_table_kernel() {
    int idx = blockIdx.x * blockDim.x + threadIdx.x;
    if (idx >= TT * 32) return;
    int t = idx / 32, i = idx % 32;
    float invf = (float)(1.0 / pow(10000.0, (double)i / 32.0));
    float ang  = (float)t * invf;           // match reference's fp32 angle
    double a = (double)ang;
    g_cos[idx] = (float)cos(a);
    g_sin[idx] = (float)sin(a);
}

// ---------------------------------------------------------------------------
// RoPE apply, in place on Q (cols 0..2047) and K (cols 2048..2559) of g_qkv.
// One thread per (row, head, i<32) rotation pair.
// ---------------------------------------------------------------------------
__global__ void rope_apply_kernel() {
    int idx = blockIdx.x * blockDim.x + threadIdx.x;
    const int PAIRS = (NH + NKV) * 32;      // 1280 per row
    if (idx >= ROWS * PAIRS) return;
    int r = idx / PAIRS;
    int p = idx % PAIRS;
    int head = p / 32, i = p % 32;
    int base = (head < NH) ? head * HDIM : (DMODEL + (head - NH) * HDIM);
    int t = r % TT;
    float c = g_cos[t * 32 + i];
    float s = g_sin[t * 32 + i];
    float* row = g_qkv + (size_t)r * QKVC + base;
    float x1 = row[i];
    float x2 = row[i + 32];
    row[i]      = x1 * c - x2 * s;
    row[i + 32] = x2 * c + x1 * s;
}

// ---------------------------------------------------------------------------
// fp32 NT GEMM: C[m, n] = sum_k A[m,k] * B[n,k].  A: M x 2048 (lda=K),
// B: N x 2048 (ldb=K), C has ldc (3072 or 2048). 128x128 tile, BK=16,
// 256 threads, 8x8 microtile. K hardcoded 2048 (all four GEMMs).
// ---------------------------------------------------------------------------
#define GK 2048
__global__ __launch_bounds__(256) void gemm_nt_kernel(
    const float* __restrict__ A, const float* __restrict__ Bm,
    float* __restrict__ C, int ldc)
{
    __shared__ float As[16][132];   // +4 pad: store conflicts -> 2-way
    __shared__ float Bs[16][132];

    const int bm = blockIdx.y * 128;
    const int bn = blockIdx.x * 128;
    const int tid = threadIdx.x;
    const int tx = tid % 16;        // column group
    const int ty = tid / 16;        // row group

    const float* Ab = A  + (size_t)bm * GK;
    const float* Bb = Bm + (size_t)bn * GK;

    float acc[8][8];
    #pragma unroll
    for (int i = 0; i < 8; i++)
        #pragma unroll
        for (int j = 0; j < 8; j++) acc[i][j] = 0.0f;

    for (int k0 = 0; k0 < GK; k0 += 16) {
        // Load A tile: 128 rows x 16 k = 512 float4s, 2 per thread
        #pragma unroll
        for (int l = tid; l < 512; l += 256) {
            int row = l >> 2;
            int kv  = l & 3;
            float4 v = *(const float4*)(Ab + (size_t)row * GK + k0 + kv * 4);
            As[kv*4+0][row] = v.x; As[kv*4+1][row] = v.y;
            As[kv*4+2][row] = v.z; As[kv*4+3][row] = v.w;
        }
        #pragma unroll
        for (int l = tid; l < 512; l += 256) {
            int row = l >> 2;
            int kv  = l & 3;
            float4 v = *(const float4*)(Bb + (size_t)row * GK + k0 + kv * 4);
            Bs[kv*4+0][row] = v.x; Bs[kv*4+1][row] = v.y;
            Bs[kv*4+2][row] = v.z; Bs[kv*4+3][row] = v.w;
        }
        __syncthreads();

        #pragma unroll
        for (int k = 0; k < 16; k++) {
            float4 a0 = *(const float4*)&As[k][ty * 8];
            float4 a1 = *(const float4*)&As[k][ty * 8 + 4];
            float4 b0 = *(const float4*)&Bs[k][tx * 8];
            float4 b1 = *(const float4*)&Bs[k][tx * 8 + 4];
            float ra[8] = {a0.x, a0.y, a0.z, a0.w, a1.x, a1.y, a1.z, a1.w};
            float rb[8] = {b0.x, b0.y, b0.z, b0.w, b1.x, b1.y, b1.z, b1.w};
            #pragma unroll
            for (int i = 0; i < 8; i++)
                #pragma unroll
                for (int j = 0; j < 8; j++)
                    acc[i][j] += ra[i] * rb[j];
        }
        __syncthreads();
    }

    float* Cb = C + (size_t)bm * ldc + bn;
    #pragma unroll
    for (int i = 0; i < 8; i++) {
        #pragma unroll
        for (int j = 0; j < 8; j += 4) {
            float4 v = make_float4(acc[i][j], acc[i][j+1], acc[i][j+2], acc[i][j+3]);
            *(float4*)(Cb + (size_t)(ty * 8 + i) * ldc + tx * 8 + j) = v;
        }
    }
}

// ---------------------------------------------------------------------------
// Causal flash attention, fp32. 64 query x 64 key tiles, 256 threads
// (16x16 grid, 4x4 fragments). Online softmax with shuffle row-reductions.
// grid = (T/64 query tiles, B*NH head problems). Only visits tiles <= diag.
// ---------------------------------------------------------------------------
__global__ __launch_bounds__(256) void flash_attn_kernel() {
    extern __shared__ float sm[];
    float (*Qs)[65] = (float(*)[65])(sm);
    float (*Ks)[65] = (float(*)[65])(sm + 64 * 65);
    float (*Vs)[65] = (float(*)[65])(sm + 2 * 64 * 65);
    float (*Ps)[65] = (float(*)[65])(sm + 3 * 64 * 65);

    const int qt = blockIdx.x;              // query tile 0..31
    const int bh = blockIdx.y;              // 0..63
    const int b  = bh / NH;
    const int h  = bh % NH;
    const int kvh = h / (NH / NKV);         // GQA map: h // 4

    const int tid = threadIdx.x;
    const int tx = tid % 16;
    const int ty = tid / 16;

    const size_t rowbase = (size_t)(b * TT) * QKVC;
    const int qcol = h * HDIM;
    const int kcol = DMODEL + kvh * HDIM;
    const int vcol = DMODEL + NKV * HDIM + kvh * HDIM;
    const float scale = 0.125f;             // 1/sqrt(64)

    // Load Q tile (64 rows x 64 dims): 1024 float4, 4 per thread
    #pragma unroll
    for (int l = tid; l < 64 * 16; l += 256) {
        int row = l >> 4, c4 = l & 15;
        float4 v = *(const float4*)(g_qkv + rowbase +
                       (size_t)(qt * 64 + row) * QKVC + qcol + c4 * 4);
        Qs[row][c4*4+0] = v.x; Qs[row][c4*4+1] = v.y;
        Qs[row][c4*4+2] = v.z; Qs[row][c4*4+3] = v.w;
    }

    float m_old[4], l_sum[4], o[4][4];
    #pragma unroll
    for (int i = 0; i < 4; i++) {
        m_old[i] = -1e30f;
        l_sum[i] = 0.0f;
        #pragma unroll
        for (int j = 0; j < 4; j++) o[i][j] = 0.0f;
    }

    for (int kt = 0; kt <= qt; kt++) {
        __syncthreads();   // protect Ks/Vs from previous iteration's readers
        #pragma unroll
        for (int l = tid; l < 64 * 16; l += 256) {
            int row = l >> 4, c4 = l & 15;
            size_t g = rowbase + (size_t)(kt * 64 + row) * QKVC;
            float4 kv4 = *(const float4*)(g_qkv + g + kcol + c4 * 4);
            float4 vv4 = *(const float4*)(g_qkv + g + vcol + c4 * 4);
            Ks[row][c4*4+0] = kv4.x; Ks[row][c4*4+1] = kv4.y;
            Ks[row][c4*4+2] = kv4.z; Ks[row][c4*4+3] = kv4.w;
            Vs[row][c4*4+0] = vv4.x; Vs[row][c4*4+1] = vv4.y;
            Vs[row][c4*4+2] = vv4.z; Vs[row][c4*4+3] = vv4.w;
        }
        __syncthreads();

        // S = (Q K^T) * scale  -- 4x4 fragment per thread
        float s[4][4];
        #pragma unroll
        for (int i = 0; i < 4; i++)
            #pragma unroll
            for (int j = 0; j < 4; j++) s[i][j] = 0.0f;

        #pragma unroll 8
        for (int d = 0; d < 64; d++) {
            float qv[4], kv[4];
            #pragma unroll
            for (int i = 0; i < 4; i++) qv[i] = Qs[4*ty+i][d];
            #pragma unroll
            for (int j = 0; j < 4; j++) kv[j] = Ks[4*tx+j][d];
            #pragma unroll
            for (int i = 0; i < 4; i++)
                #pragma unroll
                for (int j = 0; j < 4; j++)
                    s[i][j] += qv[i] * kv[j];
        }

        if (kt == qt) {  // causal mask on the diagonal tile
            #pragma unroll
            for (int i = 0; i < 4; i++) {
                int q = qt * 64 + 4 * ty + i;
                #pragma unroll
                for (int j = 0; j < 4; j++) {
                    int k = kt * 64 + 4 * tx + j;
                    s[i][j] = (k <= q) ? s[i][j] * scale : -1e30f;
                }
            }
        } else {
            #pragma unroll
            for (int i = 0; i < 4; i++)
                #pragma unroll
                for (int j = 0; j < 4; j++) s[i][j] *= scale;
        }

        // Online softmax update
        #pragma unroll
        for (int i = 0; i < 4; i++) {
            float rmax = s[i][0];
            #pragma unroll
            for (int j = 1; j < 4; j++) rmax = fmaxf(rmax, s[i][j]);
            #pragma unroll
            for (int msk = 1; msk < 16; msk <<= 1)
                rmax = fmaxf(rmax, __shfl_xor_sync(0xffffffffu, rmax, msk));

            float m_new = fmaxf(m_old[i], rmax);
            float corr  = __expf(m_old[i] - m_new);
            float rsum  = 0.0f;
            #pragma unroll
            for (int j = 0; j < 4; j++) {
                s[i][j] = __expf(s[i][j] - m_new);   // s becomes P
                rsum += s[i][j];
            }
            #pragma unroll
            for (int msk = 1; msk < 16; msk <<= 1)
                rsum += __shfl_xor_sync(0xffffffffu, rsum, msk);

            l_sum[i] = l_sum[i] * corr + rsum;
            m_old[i] = m_new;
            #pragma unroll
            for (int j = 0; j < 4; j++) o[i][j] *= corr;
        }

        // Stage P in shared (each row written & read entirely within one warp)
        #pragma unroll
        for (int i = 0; i < 4; i++)
            #pragma unroll
            for (int j = 0; j < 4; j++)
                Ps[4*ty+i][4*tx+j] = s[i][j];
        __syncwarp();

        // O += P @ V   (thread owns rows 4ty.., dims 4tx..)
        #pragma unroll 8
        for (int k = 0; k < 64; k++) {
            float pv[4], vv[4];
            #pragma unroll
            for (int i = 0; i < 4; i++) pv[i] = Ps[4*ty+i][k];
            #pragma unroll
            for (int j = 0; j < 4; j++) vv[j] = Vs[k][4*tx+j];
            #pragma unroll
            for (int i = 0; i < 4; i++)
                #pragma unroll
                for (int j = 0; j < 4; j++)
                    o[i][j] += pv[i] * vv[j];
        }
        __syncwarp();
    }

    // Normalize and write (B, T, H*hd) layout for the O-projection GEMM
    #pragma unroll
    for (int i = 0; i < 4; i++) {
        float inv = 1.0f / l_sum[i];
        int q = qt * 64 + 4 * ty + i;
        float* dst = g_att + (size_t)(b * TT + q) * DMODEL + h * HDIM + 4 * tx;
        #pragma unroll
        for (int j = 0; j < 4; j++) dst[j] = o[i][j] * inv;
    }
}

// ---------------------------------------------------------------------------
// Launch
// ---------------------------------------------------------------------------
extern "C" void kernel_launch(void* const* d_in, const int* in_sizes, int n_in,
                              void* d_out, int out_size)
{
    const float* x  = (const float*)d_in[0];
    const float* Wq = (const float*)d_in[1];
    const float* Wk = (const float*)d_in[2];
    const float* Wv = (const float*)d_in[3];
    const float* Wo = (const float*)d_in[4];
    float* out = (float*)d_out;

    float *qkv, *att;
    cudaGetSymbolAddress((void**)&qkv, g_qkv);
    cudaGetSymbolAddress((void**)&att, g_att);

    const int FLASH_SMEM = 4 * 64 * 65 * sizeof(float);   // 66560 B
    cudaFuncSetAttribute(flash_attn_kernel,
                         cudaFuncAttributeMaxDynamicSharedMemorySize, FLASH_SMEM);

    // QKV projections (NT GEMMs into packed [row][3072] buffer)
    gemm_nt_kernel<<<dim3(DMODEL / 128, ROWS / 128), 256>>>(x, Wq, qkv, QKVC);
    gemm_nt_kernel<<<dim3(512 / 128,    ROWS / 128), 256>>>(x, Wk, qkv + DMODEL, QKVC);
    gemm_nt_kernel<<<dim3(512 / 128,    ROWS / 128), 256>>>(x, Wv, qkv + DMODEL + 512, QKVC);

    // RoPE
    rope_table_kernel<<<(TT * 32 + 255) / 256, 256>>>();
    rope_apply_kernel<<<(ROWS * 1280 + 255) / 256, 256>>>();

    // Causal flash attention
    flash_attn_kernel<<<dim3(TT / 64, BB * NH), 256, FLASH_SMEM>>>();

    // Output projection
    gemm_nt_kernel<<<dim3(DMODEL / 128, ROWS / 128), 256>>>(att, Wo, out, DMODEL);
}

// round 3
// speedup vs baseline: 1.7322x; 1.7322x over previous
#include <cuda_runtime.h>
#include <cuda_bf16.h>
#include <math.h>
#include <stdint.h>

// Problem constants
#define BB      2
#define TT      2048
#define DMODEL  2048
#define NH      32
#define NKV     8
#define HDIM    64
#define QKVC    3072            // 2048 (Q) + 512 (K) + 512 (V)
#define ROWS    (BB * TT)       // 4096
#define GK      2048            // reduction dim of every GEMM

// ---------------------------------------------------------------------------
// Device scratch (allocation-free rule: __device__ globals)
// ---------------------------------------------------------------------------
__device__ float g_qkv[(size_t)ROWS * QKVC];   // [row][3072] fp32
__device__ float g_att[(size_t)ROWS * DMODEL]; // attention out (B,T,H*hd)
__device__ float g_cos[TT * 32];
__device__ float g_sin[TT * 32];

// bf16 split operands
__device__ __nv_bfloat16 g_x_hi [(size_t)ROWS * GK];
__device__ __nv_bfloat16 g_x_lo [(size_t)ROWS * GK];
__device__ __nv_bfloat16 g_w1_hi[(size_t)QKVC * GK];   // packed [Wq;Wk;Wv]
__device__ __nv_bfloat16 g_w1_lo[(size_t)QKVC * GK];
__device__ __nv_bfloat16 g_wo_hi[(size_t)DMODEL * GK];
__device__ __nv_bfloat16 g_wo_lo[(size_t)DMODEL * GK];
__device__ __nv_bfloat16 g_a_hi [(size_t)ROWS * GK];
__device__ __nv_bfloat16 g_a_lo [(size_t)ROWS * GK];

// ---------------------------------------------------------------------------
// Base-ISA PTX helpers (sm_80-class: cp.async / ldmatrix / mma.sync)
// ---------------------------------------------------------------------------
__device__ __forceinline__ uint32_t smem_u32(const void* p) {
    uint32_t a;
    asm("{ .reg .u64 t; cvta.to.shared.u64 t, %1; cvt.u32.u64 %0, t; }"
        : "=r"(a) : "l"(p));
    return a;
}
__device__ __forceinline__ void cp16(uint32_t s, const void* g) {
    asm volatile("cp.async.cg.shared.global [%0], [%1], 16;"
                 :: "r"(s), "l"(g));
}
#define CP_COMMIT() asm volatile("cp.async.commit_group;" ::: "memory")
#define CP_WAIT0()  asm volatile("cp.async.wait_group 0;" ::: "memory")
#define CP_WAIT1()  asm volatile("cp.async.wait_group 1;" ::: "memory")

__device__ __forceinline__ void ldsm4(uint32_t* r, uint32_t a) {
    asm volatile("ldmatrix.sync.aligned.m8n8.x4.shared.b16 {%0,%1,%2,%3}, [%4];"
                 : "=r"(r[0]), "=r"(r[1]), "=r"(r[2]), "=r"(r[3]) : "r"(a));
}
__device__ __forceinline__ void mma_bf16(float* d, const uint32_t* a,
                                         const uint32_t* b) {
    asm volatile(
        "mma.sync.aligned.m16n8k16.row.col.f32.bf16.bf16.f32 "
        "{%0,%1,%2,%3}, {%4,%5,%6,%7}, {%8,%9}, {%0,%1,%2,%3};"
        : "+f"(d[0]), "+f"(d[1]), "+f"(d[2]), "+f"(d[3])
        : "r"(a[0]), "r"(a[1]), "r"(a[2]), "r"(a[3]), "r"(b[0]), "r"(b[1]));
}

// XOR swizzle for 64B rows (4 x 16B chunks): conflict-free ldmatrix phases
__device__ __forceinline__ uint32_t swz(int r, int c) {
    return (uint32_t)(r * 64 + ((c ^ ((r >> 1) & 3)) << 4));
}

// ---------------------------------------------------------------------------
// fp32 -> (hi, lo) bf16 split
// ---------------------------------------------------------------------------
__global__ void split_bf16_kernel(const float* __restrict__ src,
                                  __nv_bfloat16* __restrict__ hi,
                                  __nv_bfloat16* __restrict__ lo, int n) {
    int i = blockIdx.x * blockDim.x + threadIdx.x;
    if (i >= n) return;
    float v = src[i];
    __nv_bfloat16 h = __float2bfloat16(v);
    hi[i] = h;
    lo[i] = __float2bfloat16(v - __bfloat162float(h));
}

// ---------------------------------------------------------------------------
// HMMA NT GEMM, 3-term bf16 split:  C[m,n] = sum_k A[m,k]*B[n,k]
// 128x128 CTA tile, BK=32, 8 warps (4M x 2N), warp tile 32x64.
// cp.async double-buffered smem: per stage {Ah, Al, Bh, Bl} 8KB each = 32KB.
// ---------------------------------------------------------------------------
#define STG 32768

__global__ __launch_bounds__(256) void gemm_mma_kernel(
    const __nv_bfloat16* __restrict__ Ah, const __nv_bfloat16* __restrict__ Al,
    const __nv_bfloat16* __restrict__ Bh, const __nv_bfloat16* __restrict__ Bl,
    float* __restrict__ C, int ldc)
{
    extern __shared__ char smem[];
    const uint32_t sb = smem_u32(smem);
    const int tid = threadIdx.x;
    const int lane = tid & 31;
    const int wid  = tid >> 5;
    const int wm = wid & 3;          // 0..3 -> M block of 32
    const int wn = wid >> 2;         // 0..1 -> N block of 64
    const int bm = blockIdx.y * 128;
    const int bn = blockIdx.x * 128;

    const __nv_bfloat16* ga[4] = {
        Ah + (size_t)bm * GK, Al + (size_t)bm * GK,
        Bh + (size_t)bn * GK, Bl + (size_t)bn * GK };

    float acc[2][8][4];
    #pragma unroll
    for (int mf = 0; mf < 2; mf++)
        #pragma unroll
        for (int n8 = 0; n8 < 8; n8++)
            #pragma unroll
            for (int j = 0; j < 4; j++) acc[mf][n8][j] = 0.0f;

    // stage loader: 4 tiles x 128 rows x 32 bf16 (64B/row, 4 chunks)
    const int r0 = tid >> 2, c0 = tid & 3;      // chunk 0 of this thread
    const int r1 = (tid + 256) >> 2;            // chunk 1 (c same: tid&3)
    auto load_stage = [&](int kc) {
        const uint32_t base = sb + (uint32_t)(kc & 1) * STG;
        const int k0 = kc * 32;
        #pragma unroll
        for (int t = 0; t < 4; t++) {
            cp16(base + t * 8192 + swz(r0, c0),
                 ga[t] + (size_t)r0 * GK + k0 + c0 * 8);
            cp16(base + t * 8192 + swz(r1, c0),
                 ga[t] + (size_t)r1 * GK + k0 + c0 * 8);
        }
        CP_COMMIT();
    };

    load_stage(0);

    for (int kc = 0; kc < GK / 32; kc++) {
        if (kc + 1 < GK / 32) { load_stage(kc + 1); CP_WAIT1(); }
        else                  { CP_WAIT0(); }
        __syncthreads();

        const uint32_t sA_h = sb + (uint32_t)(kc & 1) * STG;
        const uint32_t sA_l = sA_h + 8192;
        const uint32_t sB_h = sA_h + 16384;
        const uint32_t sB_l = sA_h + 24576;

        #pragma unroll
        for (int ks = 0; ks < 2; ks++) {
            uint32_t ahf[2][4], alf[2][4];
            #pragma unroll
            for (int mf = 0; mf < 2; mf++) {
                const int row = wm * 32 + mf * 16 + (lane & 15);
                const int ch  = ks * 2 + (lane >> 4);
                ldsm4(ahf[mf], sA_h + swz(row, ch));
                ldsm4(alf[mf], sA_l + swz(row, ch));
            }
            #pragma unroll
            for (int nf = 0; nf < 4; nf++) {
                const int nrow = wn * 64 + nf * 16 +
                                 ((lane & 7) | ((lane >> 4) << 3));
                const int ch = ks * 2 + ((lane >> 3) & 1);
                uint32_t bhf[4], blf[4];
                ldsm4(bhf, sB_h + swz(nrow, ch));
                ldsm4(blf, sB_l + swz(nrow, ch));
                #pragma unroll
                for (int mf = 0; mf < 2; mf++) {
                    mma_bf16(acc[mf][nf * 2],     ahf[mf], bhf);
                    mma_bf16(acc[mf][nf * 2 + 1], ahf[mf], bhf + 2);
                    mma_bf16(acc[mf][nf * 2],     ahf[mf], blf);
                    mma_bf16(acc[mf][nf * 2 + 1], ahf[mf], blf + 2);
                    mma_bf16(acc[mf][nf * 2],     alf[mf], bhf);
                    mma_bf16(acc[mf][nf * 2 + 1], alf[mf], bhf + 2);
                }
            }
        }
        __syncthreads();
    }

    // epilogue: d-frag layout m16n8 -> (row = lane>>2 [+8], col = (lane&3)*2)
    #pragma unroll
    for (int mf = 0; mf < 2; mf++) {
        const int row = bm + wm * 32 + mf * 16 + (lane >> 2);
        #pragma unroll
        for (int n8 = 0; n8 < 8; n8++) {
            const int col = bn + wn * 64 + n8 * 8 + (lane & 3) * 2;
            *(float2*)(C + (size_t)row * ldc + col) =
                make_float2(acc[mf][n8][0], acc[mf][n8][1]);
            *(float2*)(C + (size_t)(row + 8) * ldc + col) =
                make_float2(acc[mf][n8][2], acc[mf][n8][3]);
        }
    }
}

// ---------------------------------------------------------------------------
// RoPE table (double trig; fp32 angle matches the reference)
// ---------------------------------------------------------------------------
__global__ void rope_table_kernel() {
    int idx = blockIdx.x * blockDim.x + threadIdx.x;
    if (idx >= TT * 32) return;
    int t = idx / 32, i = idx % 32;
    float invf = (float)(1.0 / pow(10000.0, (double)i / 32.0));
    float ang  = (float)t * invf;
    double a = (double)ang;
    g_cos[idx] = (float)cos(a);
    g_sin[idx] = (float)sin(a);
}

__global__ void rope_apply_kernel() {
    int idx = blockIdx.x * blockDim.x + threadIdx.x;
    const int PAIRS = (NH + NKV) * 32;      // 1280 per row
    if (idx >= ROWS * PAIRS) return;
    int r = idx / PAIRS;
    int p = idx % PAIRS;
    int head = p / 32, i = p % 32;
    int base = (head < NH) ? head * HDIM : (DMODEL + (head - NH) * HDIM);
    int t = r % TT;
    float c = g_cos[t * 32 + i];
    float s = g_sin[t * 32 + i];
    float* row = g_qkv + (size_t)r * QKVC + base;
    float x1 = row[i];
    float x2 = row[i + 32];
    row[i]      = x1 * c - x2 * s;
    row[i + 32] = x2 * c + x1 * s;
}

// ---------------------------------------------------------------------------
// Causal flash attention, fp32 (unchanged from round 1)
// ---------------------------------------------------------------------------
__global__ __launch_bounds__(256) void flash_attn_kernel() {
    extern __shared__ float sm[];
    float (*Qs)[65] = (float(*)[65])(sm);
    float (*Ks)[65] = (float(*)[65])(sm + 64 * 65);
    float (*Vs)[65] = (float(*)[65])(sm + 2 * 64 * 65);
    float (*Ps)[65] = (float(*)[65])(sm + 3 * 64 * 65);

    const int qt = blockIdx.x;
    const int bh = blockIdx.y;
    const int b  = bh / NH;
    const int h  = bh % NH;
    const int kvh = h / (NH / NKV);

    const int tid = threadIdx.x;
    const int tx = tid % 16;
    const int ty = tid / 16;

    const size_t rowbase = (size_t)(b * TT) * QKVC;
    const int qcol = h * HDIM;
    const int kcol = DMODEL + kvh * HDIM;
    const int vcol = DMODEL + NKV * HDIM + kvh * HDIM;
    const float scale = 0.125f;

    #pragma unroll
    for (int l = tid; l < 64 * 16; l += 256) {
        int row = l >> 4, c4 = l & 15;
        float4 v = *(const float4*)(g_qkv + rowbase +
                       (size_t)(qt * 64 + row) * QKVC + qcol + c4 * 4);
        Qs[row][c4*4+0] = v.x; Qs[row][c4*4+1] = v.y;
        Qs[row][c4*4+2] = v.z; Qs[row][c4*4+3] = v.w;
    }

    float m_old[4], l_sum[4], o[4][4];
    #pragma unroll
    for (int i = 0; i < 4; i++) {
        m_old[i] = -1e30f;
        l_sum[i] = 0.0f;
        #pragma unroll
        for (int j = 0; j < 4; j++) o[i][j] = 0.0f;
    }

    for (int kt = 0; kt <= qt; kt++) {
        __syncthreads();
        #pragma unroll
        for (int l = tid; l < 64 * 16; l += 256) {
            int row = l >> 4, c4 = l & 15;
            size_t g = rowbase + (size_t)(kt * 64 + row) * QKVC;
            float4 kv4 = *(const float4*)(g_qkv + g + kcol + c4 * 4);
            float4 vv4 = *(const float4*)(g_qkv + g + vcol + c4 * 4);
            Ks[row][c4*4+0] = kv4.x; Ks[row][c4*4+1] = kv4.y;
            Ks[row][c4*4+2] = kv4.z; Ks[row][c4*4+3] = kv4.w;
            Vs[row][c4*4+0] = vv4.x; Vs[row][c4*4+1] = vv4.y;
            Vs[row][c4*4+2] = vv4.z; Vs[row][c4*4+3] = vv4.w;
        }
        __syncthreads();

        float s[4][4];
        #pragma unroll
        for (int i = 0; i < 4; i++)
            #pragma unroll
            for (int j = 0; j < 4; j++) s[i][j] = 0.0f;

        #pragma unroll 8
        for (int d = 0; d < 64; d++) {
            float qv[4], kv[4];
            #pragma unroll
            for (int i = 0; i < 4; i++) qv[i] = Qs[4*ty+i][d];
            #pragma unroll
            for (int j = 0; j < 4; j++) kv[j] = Ks[4*tx+j][d];
            #pragma unroll
            for (int i = 0; i < 4; i++)
                #pragma unroll
                for (int j = 0; j < 4; j++)
                    s[i][j] += qv[i] * kv[j];
        }

        if (kt == qt) {
            #pragma unroll
            for (int i = 0; i < 4; i++) {
                int q = qt * 64 + 4 * ty + i;
                #pragma unroll
                for (int j = 0; j < 4; j++) {
                    int k = kt * 64 + 4 * tx + j;
                    s[i][j] = (k <= q) ? s[i][j] * scale : -1e30f;
                }
            }
        } else {
            #pragma unroll
            for (int i = 0; i < 4; i++)
                #pragma unroll
                for (int j = 0; j < 4; j++) s[i][j] *= scale;
        }

        #pragma unroll
        for (int i = 0; i < 4; i++) {
            float rmax = s[i][0];
            #pragma unroll
            for (int j = 1; j < 4; j++) rmax = fmaxf(rmax, s[i][j]);
            #pragma unroll
            for (int msk = 1; msk < 16; msk <<= 1)
                rmax = fmaxf(rmax, __shfl_xor_sync(0xffffffffu, rmax, msk));

            float m_new = fmaxf(m_old[i], rmax);
            float corr  = __expf(m_old[i] - m_new);
            float rsum  = 0.0f;
            #pragma unroll
            for (int j = 0; j < 4; j++) {
                s[i][j] = __expf(s[i][j] - m_new);
                rsum += s[i][j];
            }
            #pragma unroll
            for (int msk = 1; msk < 16; msk <<= 1)
                rsum += __shfl_xor_sync(0xffffffffu, rsum, msk);

            l_sum[i] = l_sum[i] * corr + rsum;
            m_old[i] = m_new;
            #pragma unroll
            for (int j = 0; j < 4; j++) o[i][j] *= corr;
        }

        #pragma unroll
        for (int i = 0; i < 4; i++)
            #pragma unroll
            for (int j = 0; j < 4; j++)
                Ps[4*ty+i][4*tx+j] = s[i][j];
        __syncwarp();

        #pragma unroll 8
        for (int k = 0; k < 64; k++) {
            float pv[4], vv[4];
            #pragma unroll
            for (int i = 0; i < 4; i++) pv[i] = Ps[4*ty+i][k];
            #pragma unroll
            for (int j = 0; j < 4; j++) vv[j] = Vs[k][4*tx+j];
            #pragma unroll
            for (int i = 0; i < 4; i++)
                #pragma unroll
                for (int j = 0; j < 4; j++)
                    o[i][j] += pv[i] * vv[j];
        }
        __syncwarp();
    }

    #pragma unroll
    for (int i = 0; i < 4; i++) {
        float inv = 1.0f / l_sum[i];
        int q = qt * 64 + 4 * ty + i;
        float* dst = g_att + (size_t)(b * TT + q) * DMODEL + h * HDIM + 4 * tx;
        #pragma unroll
        for (int j = 0; j < 4; j++) dst[j] = o[i][j] * inv;
    }
}

// ---------------------------------------------------------------------------
// Launch
// ---------------------------------------------------------------------------
extern "C" void kernel_launch(void* const* d_in, const int* in_sizes, int n_in,
                              void* d_out, int out_size)
{
    const float* x  = (const float*)d_in[0];
    const float* Wq = (const float*)d_in[1];
    const float* Wk = (const float*)d_in[2];
    const float* Wv = (const float*)d_in[3];
    const float* Wo = (const float*)d_in[4];
    float* out = (float*)d_out;

    float *qkv, *att;
    __nv_bfloat16 *xh, *xl, *w1h, *w1l, *woh, *wol, *ah, *al;
    cudaGetSymbolAddress((void**)&qkv, g_qkv);
    cudaGetSymbolAddress((void**)&att, g_att);
    cudaGetSymbolAddress((void**)&xh,  g_x_hi);
    cudaGetSymbolAddress((void**)&xl,  g_x_lo);
    cudaGetSymbolAddress((void**)&w1h, g_w1_hi);
    cudaGetSymbolAddress((void**)&w1l, g_w1_lo);
    cudaGetSymbolAddress((void**)&woh, g_wo_hi);
    cudaGetSymbolAddress((void**)&wol, g_wo_lo);
    cudaGetSymbolAddress((void**)&ah,  g_a_hi);
    cudaGetSymbolAddress((void**)&al,  g_a_lo);

    const int GEMM_SMEM  = 2 * STG;                       // 65536 B
    const int FLASH_SMEM = 4 * 64 * 65 * sizeof(float);   // 66560 B
    cudaFuncSetAttribute(gemm_mma_kernel,
                         cudaFuncAttributeMaxDynamicSharedMemorySize, GEMM_SMEM);
    cudaFuncSetAttribute(flash_attn_kernel,
                         cudaFuncAttributeMaxDynamicSharedMemorySize, FLASH_SMEM);

    // bf16 splits: x, [Wq;Wk;Wv] packed, Wo
    {
        int n;
        n = ROWS * GK;
        split_bf16_kernel<<<(n + 255) / 256, 256>>>(x, xh, xl, n);
        n = DMODEL * GK;
        split_bf16_kernel<<<(n + 255) / 256, 256>>>(Wq, w1h, w1l, n);
        n = 512 * GK;
        split_bf16_kernel<<<(n + 255) / 256, 256>>>(Wk, w1h + (size_t)2048 * GK,
                                                        w1l + (size_t)2048 * GK, n);
        split_bf16_kernel<<<(n + 255) / 256, 256>>>(Wv, w1h + (size_t)2560 * GK,
                                                        w1l + (size_t)2560 * GK, n);
        n = DMODEL * GK;
        split_bf16_kernel<<<(n + 255) / 256, 256>>>(Wo, woh, wol, n);
    }

    // QKV projection: [4096 x 3072] = x @ Wqkv^T  (HMMA)
    gemm_mma_kernel<<<dim3(QKVC / 128, ROWS / 128), 256, GEMM_SMEM>>>(
        xh, xl, w1h, w1l, qkv, QKVC);

    // RoPE
    rope_table_kernel<<<(TT * 32 + 255) / 256, 256>>>();
    rope_apply_kernel<<<(ROWS * 1280 + 255) / 256, 256>>>();

    // Causal flash attention (fp32)
    flash_attn_kernel<<<dim3(TT / 64, BB * NH), 256, FLASH_SMEM>>>();

    // split attention output, then O projection (HMMA)
    {
        int n = ROWS * GK;
        split_bf16_kernel<<<(n + 255) / 256, 256>>>(att, ah, al, n);
    }
    gemm_mma_kernel<<<dim3(DMODEL / 128, ROWS / 128), 256, GEMM_SMEM>>>(
        ah, al, woh, wol, out, DMODEL);
}

// round 4
// speedup vs baseline: 2.9569x; 1.7071x over previous
#include <cuda_runtime.h>
#include <cuda_bf16.h>
#include <math.h>
#include <stdint.h>

// Problem constants
#define BB      2
#define TT      2048
#define DMODEL  2048
#define NH      32
#define NKV     8
#define HDIM    64
#define QKVC    3072            // 2048 (Q) + 512 (K) + 512 (V)
#define ROWS    (BB * TT)       // 4096
#define GK      2048            // reduction dim of the projection GEMMs

// ---------------------------------------------------------------------------
// Device scratch (allocation-free rule: __device__ globals)
// ---------------------------------------------------------------------------
__device__ float g_qkv[(size_t)ROWS * QKVC];   // [row][3072] fp32
__device__ float g_cos[TT * 32];
__device__ float g_sin[TT * 32];

// bf16 split operands for projection GEMMs
__device__ __nv_bfloat16 g_x_hi [(size_t)ROWS * GK];
__device__ __nv_bfloat16 g_x_lo [(size_t)ROWS * GK];
__device__ __nv_bfloat16 g_w1_hi[(size_t)QKVC * GK];   // packed [Wq;Wk;Wv]
__device__ __nv_bfloat16 g_w1_lo[(size_t)QKVC * GK];
__device__ __nv_bfloat16 g_wo_hi[(size_t)DMODEL * GK];
__device__ __nv_bfloat16 g_wo_lo[(size_t)DMODEL * GK];
__device__ __nv_bfloat16 g_a_hi [(size_t)ROWS * GK];   // attention O hi (A of O-proj)
__device__ __nv_bfloat16 g_a_lo [(size_t)ROWS * GK];   // attention O lo

// bf16 split Q/K/V, head-major layouts
__device__ __nv_bfloat16 g_qh[(size_t)ROWS * DMODEL];  // [b][h][t][64]
__device__ __nv_bfloat16 g_ql[(size_t)ROWS * DMODEL];
__device__ __nv_bfloat16 g_kh[(size_t)BB * NKV * TT * HDIM]; // [b][kv][t][64]
__device__ __nv_bfloat16 g_kl[(size_t)BB * NKV * TT * HDIM];
__device__ __nv_bfloat16 g_vh[(size_t)BB * NKV * TT * HDIM];
__device__ __nv_bfloat16 g_vl[(size_t)BB * NKV * TT * HDIM];

// ---------------------------------------------------------------------------
// Base-ISA PTX helpers (sm_80-class: cp.async / ldmatrix / mma.sync)
// ---------------------------------------------------------------------------
__device__ __forceinline__ uint32_t smem_u32(const void* p) {
    uint32_t a;
    asm("{ .reg .u64 t; cvta.to.shared.u64 t, %1; cvt.u32.u64 %0, t; }"
        : "=r"(a) : "l"(p));
    return a;
}
__device__ __forceinline__ void cp16(uint32_t s, const void* g) {
    asm volatile("cp.async.cg.shared.global [%0], [%1], 16;"
                 :: "r"(s), "l"(g));
}
#define CP_COMMIT() asm volatile("cp.async.commit_group;" ::: "memory")
#define CP_WAIT0()  asm volatile("cp.async.wait_group 0;" ::: "memory")
#define CP_WAIT1()  asm volatile("cp.async.wait_group 1;" ::: "memory")

__device__ __forceinline__ void ldsm4(uint32_t* r, uint32_t a) {
    asm volatile("ldmatrix.sync.aligned.m8n8.x4.shared.b16 {%0,%1,%2,%3}, [%4];"
                 : "=r"(r[0]), "=r"(r[1]), "=r"(r[2]), "=r"(r[3]) : "r"(a));
}
__device__ __forceinline__ void ldsm4t(uint32_t* r, uint32_t a) {
    asm volatile("ldmatrix.sync.aligned.m8n8.x4.trans.shared.b16 {%0,%1,%2,%3}, [%4];"
                 : "=r"(r[0]), "=r"(r[1]), "=r"(r[2]), "=r"(r[3]) : "r"(a));
}
__device__ __forceinline__ void mma_bf16(float* d, const uint32_t* a,
                                         const uint32_t* b) {
    asm volatile(
        "mma.sync.aligned.m16n8k16.row.col.f32.bf16.bf16.f32 "
        "{%0,%1,%2,%3}, {%4,%5,%6,%7}, {%8,%9}, {%0,%1,%2,%3};"
        : "+f"(d[0]), "+f"(d[1]), "+f"(d[2]), "+f"(d[3])
        : "r"(a[0]), "r"(a[1]), "r"(a[2]), "r"(a[3]), "r"(b[0]), "r"(b[1]));
}
// pack two fp32 -> bf16x2 (lo goes to low 16 bits)
__device__ __forceinline__ uint32_t packbf(float lo, float hi) {
    __nv_bfloat162 t = __floats2bfloat162_rn(lo, hi);
    return *(uint32_t*)&t;
}

// XOR swizzle, 64B rows (4 x 16B chunks) — projection GEMM tiles
__device__ __forceinline__ uint32_t swz(int r, int c) {
    return (uint32_t)(r * 64 + ((c ^ ((r >> 1) & 3)) << 4));
}
// XOR swizzle, 128B rows (8 x 16B chunks) — attention tiles
__device__ __forceinline__ uint32_t sw8(int r, int c) {
    return (uint32_t)(r * 128 + ((c ^ (r & 7)) << 4));
}

// ---------------------------------------------------------------------------
// fp32 -> (hi, lo) bf16 split (flat)
// ---------------------------------------------------------------------------
__global__ void split_bf16_kernel(const float* __restrict__ src,
                                  __nv_bfloat16* __restrict__ hi,
                                  __nv_bfloat16* __restrict__ lo, int n) {
    int i = blockIdx.x * blockDim.x + threadIdx.x;
    if (i >= n) return;
    float v = src[i];
    __nv_bfloat16 h = __float2bfloat16(v);
    hi[i] = h;
    lo[i] = __float2bfloat16(v - __bfloat162float(h));
}

// ---------------------------------------------------------------------------
// Split + rearrange post-RoPE QKV into head-major bf16 hi/lo buffers.
// One thread per 4 consecutive elements (always within one head's 64 dims).
// ---------------------------------------------------------------------------
__global__ void qkv_split_kernel() {
    int idx = blockIdx.x * blockDim.x + threadIdx.x;
    if (idx >= ROWS * QKVC / 4) return;
    int i4  = idx * 4;
    int row = i4 / QKVC;
    int col = i4 % QKVC;
    int b = row / TT, t = row % TT;

    float4 v = *(const float4*)(g_qkv + (size_t)row * QKVC + col);
    float f[4] = {v.x, v.y, v.z, v.w};
    __nv_bfloat16 h[4], l[4];
    #pragma unroll
    for (int j = 0; j < 4; j++) {
        h[j] = __float2bfloat16(f[j]);
        l[j] = __float2bfloat16(f[j] - __bfloat162float(h[j]));
    }
    uint2 hv = make_uint2(packbf(__bfloat162float(h[0]), __bfloat162float(h[1])),
                          packbf(__bfloat162float(h[2]), __bfloat162float(h[3])));
    // packbf rounds again but inputs are exact bf16 values -> identity
    uint2 lv = make_uint2(packbf(__bfloat162float(l[0]), __bfloat162float(l[1])),
                          packbf(__bfloat162float(l[2]), __bfloat162float(l[3])));

    if (col < DMODEL) {
        int hh = col >> 6, d = col & 63;
        size_t dst = ((size_t)(b * NH + hh) * TT + t) * HDIM + d;
        *(uint2*)(g_qh + dst) = hv;
        *(uint2*)(g_ql + dst) = lv;
    } else if (col < DMODEL + 512) {
        int c2 = col - DMODEL;
        int kv = c2 >> 6, d = c2 & 63;
        size_t dst = ((size_t)(b * NKV + kv) * TT + t) * HDIM + d;
        *(uint2*)(g_kh + dst) = hv;
        *(uint2*)(g_kl + dst) = lv;
    } else {
        int c2 = col - DMODEL - 512;
        int kv = c2 >> 6, d = c2 & 63;
        size_t dst = ((size_t)(b * NKV + kv) * TT + t) * HDIM + d;
        *(uint2*)(g_vh + dst) = hv;
        *(uint2*)(g_vl + dst) = lv;
    }
}

// ---------------------------------------------------------------------------
// HMMA NT GEMM, 3-term bf16 split (unchanged from round 3)
// ---------------------------------------------------------------------------
#define STG 32768

__global__ __launch_bounds__(256) void gemm_mma_kernel(
    const __nv_bfloat16* __restrict__ Ah, const __nv_bfloat16* __restrict__ Al,
    const __nv_bfloat16* __restrict__ Bh, const __nv_bfloat16* __restrict__ Bl,
    float* __restrict__ C, int ldc)
{
    extern __shared__ char smem[];
    const uint32_t sb = smem_u32(smem);
    const int tid = threadIdx.x;
    const int lane = tid & 31;
    const int wid  = tid >> 5;
    const int wm = wid & 3;
    const int wn = wid >> 2;
    const int bm = blockIdx.y * 128;
    const int bn = blockIdx.x * 128;

    const __nv_bfloat16* ga[4] = {
        Ah + (size_t)bm * GK, Al + (size_t)bm * GK,
        Bh + (size_t)bn * GK, Bl + (size_t)bn * GK };

    float acc[2][8][4];
    #pragma unroll
    for (int mf = 0; mf < 2; mf++)
        #pragma unroll
        for (int n8 = 0; n8 < 8; n8++)
            #pragma unroll
            for (int j = 0; j < 4; j++) acc[mf][n8][j] = 0.0f;

    const int r0 = tid >> 2, c0 = tid & 3;
    const int r1 = (tid + 256) >> 2;
    auto load_stage = [&](int kc) {
        const uint32_t base = sb + (uint32_t)(kc & 1) * STG;
        const int k0 = kc * 32;
        #pragma unroll
        for (int t = 0; t < 4; t++) {
            cp16(base + t * 8192 + swz(r0, c0),
                 ga[t] + (size_t)r0 * GK + k0 + c0 * 8);
            cp16(base + t * 8192 + swz(r1, c0),
                 ga[t] + (size_t)r1 * GK + k0 + c0 * 8);
        }
        CP_COMMIT();
    };

    load_stage(0);

    for (int kc = 0; kc < GK / 32; kc++) {
        if (kc + 1 < GK / 32) { load_stage(kc + 1); CP_WAIT1(); }
        else                  { CP_WAIT0(); }
        __syncthreads();

        const uint32_t sA_h = sb + (uint32_t)(kc & 1) * STG;
        const uint32_t sA_l = sA_h + 8192;
        const uint32_t sB_h = sA_h + 16384;
        const uint32_t sB_l = sA_h + 24576;

        #pragma unroll
        for (int ks = 0; ks < 2; ks++) {
            uint32_t ahf[2][4], alf[2][4];
            #pragma unroll
            for (int mf = 0; mf < 2; mf++) {
                const int row = wm * 32 + mf * 16 + (lane & 15);
                const int ch  = ks * 2 + (lane >> 4);
                ldsm4(ahf[mf], sA_h + swz(row, ch));
                ldsm4(alf[mf], sA_l + swz(row, ch));
            }
            #pragma unroll
            for (int nf = 0; nf < 4; nf++) {
                const int nrow = wn * 64 + nf * 16 +
                                 ((lane & 7) | ((lane >> 4) << 3));
                const int ch = ks * 2 + ((lane >> 3) & 1);
                uint32_t bhf[4], blf[4];
                ldsm4(bhf, sB_h + swz(nrow, ch));
                ldsm4(blf, sB_l + swz(nrow, ch));
                #pragma unroll
                for (int mf = 0; mf < 2; mf++) {
                    mma_bf16(acc[mf][nf * 2],     ahf[mf], bhf);
                    mma_bf16(acc[mf][nf * 2 + 1], ahf[mf], bhf + 2);
                    mma_bf16(acc[mf][nf * 2],     ahf[mf], blf);
                    mma_bf16(acc[mf][nf * 2 + 1], ahf[mf], blf + 2);
                    mma_bf16(acc[mf][nf * 2],     alf[mf], bhf);
                    mma_bf16(acc[mf][nf * 2 + 1], alf[mf], bhf + 2);
                }
            }
        }
        __syncthreads();
    }

    #pragma unroll
    for (int mf = 0; mf < 2; mf++) {
        const int row = bm + wm * 32 + mf * 16 + (lane >> 2);
        #pragma unroll
        for (int n8 = 0; n8 < 8; n8++) {
            const int col = bn + wn * 64 + n8 * 8 + (lane & 3) * 2;
            *(float2*)(C + (size_t)row * ldc + col) =
                make_float2(acc[mf][n8][0], acc[mf][n8][1]);
            *(float2*)(C + (size_t)(row + 8) * ldc + col) =
                make_float2(acc[mf][n8][2], acc[mf][n8][3]);
        }
    }
}

// ---------------------------------------------------------------------------
// RoPE table + in-place apply (unchanged)
// ---------------------------------------------------------------------------
__global__ void rope_table_kernel() {
    int idx = blockIdx.x * blockDim.x + threadIdx.x;
    if (idx >= TT * 32) return;
    int t = idx / 32, i = idx % 32;
    float invf = (float)(1.0 / pow(10000.0, (double)i / 32.0));
    float ang  = (float)t * invf;
    double a = (double)ang;
    g_cos[idx] = (float)cos(a);
    g_sin[idx] = (float)sin(a);
}

__global__ void rope_apply_kernel() {
    int idx = blockIdx.x * blockDim.x + threadIdx.x;
    const int PAIRS = (NH + NKV) * 32;
    if (idx >= ROWS * PAIRS) return;
    int r = idx / PAIRS;
    int p = idx % PAIRS;
    int head = p / 32, i = p % 32;
    int base = (head < NH) ? head * HDIM : (DMODEL + (head - NH) * HDIM);
    int t = r % TT;
    float c = g_cos[t * 32 + i];
    float s = g_sin[t * 32 + i];
    float* row = g_qkv + (size_t)r * QKVC + base;
    float x1 = row[i];
    float x2 = row[i + 32];
    row[i]      = x1 * c - x2 * s;
    row[i + 32] = x2 * c + x1 * s;
}

// ---------------------------------------------------------------------------
// Tensor-core causal flash attention.
// CTA: 128 q-rows, 8 warps (16 rows each), K-tiles of 64 keys.
// smem: Qh/Ql staged once (16KB each); K/V hi/lo double-buffered (8KB each).
// S = Qh.Kh + Qh.Kl + Ql.Kh ; softmax fp32 ; O += Ph.Vh + Ph.Vl + Pl.Vh.
// Epilogue writes bf16 hi/lo of O straight into the O-projection A operand.
// ---------------------------------------------------------------------------
#define FA_Q_OFF   0
#define FA_KV_OFF  32768
#define FA_STAGE   32768
#define FA_SMEM    (FA_KV_OFF + 2 * FA_STAGE)   // 98304

__global__ __launch_bounds__(256) void flash_mma_kernel() {
    extern __shared__ char smem[];
    const uint32_t sb = smem_u32(smem);
    const int tid  = threadIdx.x;
    const int lane = tid & 31;
    const int wid  = tid >> 5;

    const int qt = blockIdx.x;              // 0..15
    const int bh = blockIdx.y;              // 0..63
    const int b  = bh / NH;
    const int h  = bh % NH;
    const int kvh = h / (NH / NKV);

    const __nv_bfloat16* qhp = g_qh + ((size_t)(b * NH + h) * TT + qt * 128) * HDIM;
    const __nv_bfloat16* qlp = g_ql + ((size_t)(b * NH + h) * TT + qt * 128) * HDIM;
    const size_t kvbase = (size_t)(b * NKV + kvh) * TT * HDIM;

    const uint32_t sQh = sb + FA_Q_OFF;
    const uint32_t sQl = sQh + 16384;

    // ---- async load Q (128 rows x 64 bf16, hi+lo), group 0 part 1 ----
    {
        const int r = tid >> 1;              // 0..127
        const int cc = (tid & 1) * 4;        // chunks 0-3 / 4-7
        #pragma unroll
        for (int j = 0; j < 4; j++) {
            cp16(sQh + sw8(r, cc + j), qhp + (size_t)r * HDIM + (cc + j) * 8);
            cp16(sQl + sw8(r, cc + j), qlp + (size_t)r * HDIM + (cc + j) * 8);
        }
    }
    // KV stage loader: {Kh, Kl, Vh, Vl} 64x64 each
    const int kr = tid >> 1;                 // 0..127 -> row = kr&63, half sel
    auto load_stage = [&](int kt) {
        const uint32_t base = sb + FA_KV_OFF + (uint32_t)(kt & 1) * FA_STAGE;
        const int r = kr & 63;
        const int cc = ((kr >> 6) * 4 + 0);  // rows done twice: chunks 0-3 or 4-7
        const int c4 = ((tid & 1) * 2) + ((kr >> 6) * 4); // not used; simpler below
        (void)cc; (void)c4;
        // each thread: row r, 4 chunks (half row), for 4 tiles
        const int ch0 = (kr >> 6) * 4 + 0;   // 0 or 4
        const size_t gro = kvbase + (size_t)(kt * 64 + r) * HDIM;
        #pragma unroll
        for (int j = 0; j < 2; j++) {
            int ch = ch0 + (tid & 1) * 2 + j;   // wrong spread? see note
            (void)ch;
        }
        // NOTE: simpler deterministic mapping: 256 threads x 8 cp16 = 2048 chunks
        #pragma unroll
        for (int t4 = 0; t4 < 4; t4++) {
            const uint32_t tb = base + t4 * 8192;
            const __nv_bfloat16* gp =
                (t4 == 0) ? g_kh : (t4 == 1) ? g_kl : (t4 == 2) ? g_vh : g_vl;
            // thread covers 2 chunks of its row-half
            const int ch_a = (kr >> 6) * 4 + (tid & 1) * 2;
            cp16(tb + sw8(r, ch_a),     gp + gro + ch_a * 8);
            cp16(tb + sw8(r, ch_a + 1), gp + gro + (ch_a + 1) * 8);
        }
    };
    // Fix thread->chunk mapping: kr in [0,128): r = kr & 63; kr>>6 selects chunk half.
    // (tid&1) further splits: chunks {half*4 + (tid&1)*2, +1}. With tid = kr*2+(tid&1),
    // all 8 chunks x 64 rows covered exactly once per tile.

    load_stage(0);
    CP_COMMIT();

    // per-thread state: rows r=lane>>2 and r+8 within the warp's 16 rows
    float m_old[2] = {-1e30f, -1e30f};
    float l_sum[2] = {0.0f, 0.0f};
    float oacc[8][4];
    #pragma unroll
    for (int n8 = 0; n8 < 8; n8++)
        #pragma unroll
        for (int j = 0; j < 4; j++) oacc[n8][j] = 0.0f;

    const int nkt = 2 * qt + 2;
    const int rowg0 = qt * 128 + wid * 16 + (lane >> 2);  // rh=0 global q row

    for (int kt = 0; kt < nkt; kt++) {
        if (kt + 1 < nkt) { load_stage(kt + 1); CP_COMMIT(); CP_WAIT1(); }
        else              { CP_WAIT0(); }
        __syncthreads();

        const uint32_t kvb = sb + FA_KV_OFF + (uint32_t)(kt & 1) * FA_STAGE;
        const uint32_t sKh = kvb,          sKl = kvb + 8192;
        const uint32_t sVh = kvb + 16384,  sVl = kvb + 24576;

        // ---- S = Q K^T (3-term) ----
        float sacc[8][4];
        #pragma unroll
        for (int n8 = 0; n8 < 8; n8++)
            #pragma unroll
            for (int j = 0; j < 4; j++) sacc[n8][j] = 0.0f;

        #pragma unroll
        for (int ks = 0; ks < 4; ks++) {
            uint32_t qh[4], ql[4];
            const int qrow = wid * 16 + (lane & 15);
            const int qch  = ks * 2 + (lane >> 4);
            ldsm4(qh, sQh + sw8(qrow, qch));
            ldsm4(ql, sQl + sw8(qrow, qch));
            #pragma unroll
            for (int nf = 0; nf < 4; nf++) {
                const int nrow = nf * 16 + ((lane & 7) | ((lane >> 4) << 3));
                const int nch  = ks * 2 + ((lane >> 3) & 1);
                uint32_t khf[4], klf[4];
                ldsm4(khf, sKh + sw8(nrow, nch));
                ldsm4(klf, sKl + sw8(nrow, nch));
                mma_bf16(sacc[nf * 2],     qh, khf);
                mma_bf16(sacc[nf * 2 + 1], qh, khf + 2);
                mma_bf16(sacc[nf * 2],     qh, klf);
                mma_bf16(sacc[nf * 2 + 1], qh, klf + 2);
                mma_bf16(sacc[nf * 2],     ql, khf);
                mma_bf16(sacc[nf * 2 + 1], ql, khf + 2);
            }
        }

        // ---- scale + causal mask ----
        const bool diag = (kt >= 2 * qt);        // only last two tiles need mask
        #pragma unroll
        for (int n8 = 0; n8 < 8; n8++) {
            #pragma unroll
            for (int j = 0; j < 4; j++) {
                float v = sacc[n8][j] * 0.125f;
                if (diag) {
                    int rg = rowg0 + (j >> 1) * 8;
                    int cg = kt * 64 + n8 * 8 + (lane & 3) * 2 + (j & 1);
                    if (cg > rg) v = -1e30f;
                }
                sacc[n8][j] = v;
            }
        }

        // ---- online softmax ----
        #pragma unroll
        for (int rh = 0; rh < 2; rh++) {
            float mx = -1e30f;
            #pragma unroll
            for (int n8 = 0; n8 < 8; n8++) {
                mx = fmaxf(mx, sacc[n8][rh * 2]);
                mx = fmaxf(mx, sacc[n8][rh * 2 + 1]);
            }
            mx = fmaxf(mx, __shfl_xor_sync(0xffffffffu, mx, 1));
            mx = fmaxf(mx, __shfl_xor_sync(0xffffffffu, mx, 2));

            float mnew = fmaxf(m_old[rh], mx);
            float corr = __expf(m_old[rh] - mnew);
            float sum  = 0.0f;
            #pragma unroll
            for (int n8 = 0; n8 < 8; n8++) {
                float p0 = __expf(sacc[n8][rh * 2]     - mnew);
                float p1 = __expf(sacc[n8][rh * 2 + 1] - mnew);
                sacc[n8][rh * 2]     = p0;
                sacc[n8][rh * 2 + 1] = p1;
                sum += p0 + p1;
            }
            sum += __shfl_xor_sync(0xffffffffu, sum, 1);
            sum += __shfl_xor_sync(0xffffffffu, sum, 2);
            l_sum[rh] = l_sum[rh] * corr + sum;
            m_old[rh] = mnew;
            #pragma unroll
            for (int n8 = 0; n8 < 8; n8++) {
                oacc[n8][rh * 2]     *= corr;
                oacc[n8][rh * 2 + 1] *= corr;
            }
        }

        // ---- O += P V (3-term, P split in registers) ----
        #pragma unroll
        for (int kb = 0; kb < 4; kb++) {
            uint32_t aph[4], apl[4];
            #pragma unroll
            for (int q2 = 0; q2 < 2; q2++) {           // the two n8 blocks of this k16
                const int n8 = kb * 2 + q2;
                #pragma unroll
                for (int rr = 0; rr < 2; rr++) {       // c0c1 / c2c3
                    float p0 = sacc[n8][rr * 2];
                    float p1 = sacc[n8][rr * 2 + 1];
                    __nv_bfloat162 hcv = __floats2bfloat162_rn(p0, p1);
                    float r0 = p0 - __bfloat162float(hcv.x);
                    float r1 = p1 - __bfloat162float(hcv.y);
                    aph[q2 * 2 + rr] = *(uint32_t*)&hcv;
                    apl[q2 * 2 + rr] = packbf(r0, r1);
                }
            }
            #pragma unroll
            for (int db = 0; db < 4; db++) {
                const int vrow = kb * 16 + (lane & 15);
                const int vch  = db * 2 + (lane >> 4);
                uint32_t vhf[4], vlf[4];
                ldsm4t(vhf, sVh + sw8(vrow, vch));
                ldsm4t(vlf, sVl + sw8(vrow, vch));
                mma_bf16(oacc[db * 2],     aph, vhf);
                mma_bf16(oacc[db * 2 + 1], aph, vhf + 2);
                mma_bf16(oacc[db * 2],     aph, vlf);
                mma_bf16(oacc[db * 2 + 1], aph, vlf + 2);
                mma_bf16(oacc[db * 2],     apl, vhf);
                mma_bf16(oacc[db * 2 + 1], apl, vhf + 2);
            }
        }
        __syncthreads();
    }

    // ---- epilogue: normalize, split to bf16 hi/lo, write O-proj A operand ----
    #pragma unroll
    for (int rh = 0; rh < 2; rh++) {
        const float inv = 1.0f / l_sum[rh];
        const int rowg = (b * TT) + rowg0 + rh * 8;     // global row in [row][2048]
        #pragma unroll
        for (int n8 = 0; n8 < 8; n8++) {
            const int col = h * HDIM + n8 * 8 + (lane & 3) * 2;
            float o0 = oacc[n8][rh * 2] * inv;
            float o1 = oacc[n8][rh * 2 + 1] * inv;
            __nv_bfloat162 hv = __floats2bfloat162_rn(o0, o1);
            float r0 = o0 - __bfloat162float(hv.x);
            float r1 = o1 - __bfloat162float(hv.y);
            *(uint32_t*)(g_a_hi + (size_t)rowg * GK + col) = *(uint32_t*)&hv;
            *(uint32_t*)(g_a_lo + (size_t)rowg * GK + col) = packbf(r0, r1);
        }
    }
}

// ---------------------------------------------------------------------------
// Launch
// ---------------------------------------------------------------------------
extern "C" void kernel_launch(void* const* d_in, const int* in_sizes, int n_in,
                              void* d_out, int out_size)
{
    const float* x  = (const float*)d_in[0];
    const float* Wq = (const float*)d_in[1];
    const float* Wk = (const float*)d_in[2];
    const float* Wv = (const float*)d_in[3];
    const float* Wo = (const float*)d_in[4];
    float* out = (float*)d_out;

    float* qkv;
    __nv_bfloat16 *xh, *xl, *w1h, *w1l, *woh, *wol, *ah, *al;
    cudaGetSymbolAddress((void**)&qkv, g_qkv);
    cudaGetSymbolAddress((void**)&xh,  g_x_hi);
    cudaGetSymbolAddress((void**)&xl,  g_x_lo);
    cudaGetSymbolAddress((void**)&w1h, g_w1_hi);
    cudaGetSymbolAddress((void**)&w1l, g_w1_lo);
    cudaGetSymbolAddress((void**)&woh, g_wo_hi);
    cudaGetSymbolAddress((void**)&wol, g_wo_lo);
    cudaGetSymbolAddress((void**)&ah,  g_a_hi);
    cudaGetSymbolAddress((void**)&al,  g_a_lo);

    const int GEMM_SMEM = 2 * STG;                        // 65536
    cudaFuncSetAttribute(gemm_mma_kernel,
                         cudaFuncAttributeMaxDynamicSharedMemorySize, GEMM_SMEM);
    cudaFuncSetAttribute(flash_mma_kernel,
                         cudaFuncAttributeMaxDynamicSharedMemorySize, FA_SMEM);

    // bf16 splits of x and weights
    {
        int n;
        n = ROWS * GK;
        split_bf16_kernel<<<(n + 255) / 256, 256>>>(x, xh, xl, n);
        n = DMODEL * GK;
        split_bf16_kernel<<<(n + 255) / 256, 256>>>(Wq, w1h, w1l, n);
        n = 512 * GK;
        split_bf16_kernel<<<(n + 255) / 256, 256>>>(Wk, w1h + (size_t)2048 * GK,
                                                        w1l + (size_t)2048 * GK, n);
        split_bf16_kernel<<<(n + 255) / 256, 256>>>(Wv, w1h + (size_t)2560 * GK,
                                                        w1l + (size_t)2560 * GK, n);
        n = DMODEL * GK;
        split_bf16_kernel<<<(n + 255) / 256, 256>>>(Wo, woh, wol, n);
    }

    // QKV projection (HMMA)
    gemm_mma_kernel<<<dim3(QKVC / 128, ROWS / 128), 256, GEMM_SMEM>>>(
        xh, xl, w1h, w1l, qkv, QKVC);

    // RoPE, then split+rearrange into head-major bf16 hi/lo
    rope_table_kernel<<<(TT * 32 + 255) / 256, 256>>>();
    rope_apply_kernel<<<(ROWS * 1280 + 255) / 256, 256>>>();
    qkv_split_kernel<<<(ROWS * QKVC / 4 + 255) / 256, 256>>>();

    // Tensor-core causal flash attention (writes O-proj A operand directly)
    flash_mma_kernel<<<dim3(TT / 128, BB * NH), 256, FA_SMEM>>>();

    // Output projection (HMMA)
    gemm_mma_kernel<<<dim3(DMODEL / 128, ROWS / 128), 256, GEMM_SMEM>>>(
        ah, al, woh, wol, out, DMODEL);
}